// round 3
// baseline (speedup 1.0000x reference)
#include <cuda_runtime.h>
#include <cuda_bf16.h>

#define HLR 128
#define WLR 128
#define HH 512
#define WH 512
#define CC 64
#define NPIX (HH*WH)      // 262144
#define NQ 262144

// ---- scratch (device globals: allocation-free) ----
__device__ __align__(16) float g_feat[NPIX/16*CC];   // 4 MB, channel-LAST [y*128+x][c]
__device__ __align__(16) float g_hidden[CC*NPIX];    // 64 MB, channel-FIRST [c][y][x]
__device__ __align__(16) float g_pred[3*NPIX];       // 3 MB  [o][y][x]
__device__ float g_off[16*2];
__device__ float g_r[16*4];
__device__ float g_A[16*512];            // [ph][c][k]  (64x8)
__device__ float g_B[16*512];            // [ph][k][c]  (8x64)

// ---------------- Kernel 1: encoder conv3x3 (3 -> 64, 128x128) -> channel-last ----------------
__global__ void __launch_bounds__(128)
enc_conv(const float* __restrict__ inp,
         const float* __restrict__ w,
         const float* __restrict__ b) {
    __shared__ float sw[27*64];   // [j][c]
    __shared__ float sb[64];
    for (int idx = threadIdx.x; idx < 27*64; idx += 128) {
        int j = idx >> 6, c = idx & 63;
        sw[idx] = __ldg(&w[c*27 + j]);
    }
    if (threadIdx.x < 64) sb[threadIdx.x] = __ldg(&b[threadIdx.x]);
    __syncthreads();

    int t = blockIdx.x*128 + threadIdx.x;   // pixel
    int x = t & 127, y = t >> 7;

    float in[27];
    #pragma unroll
    for (int ci = 0; ci < 3; ci++)
        #pragma unroll
        for (int ky = 0; ky < 3; ky++) {
            int yy = y + ky - 1;
            bool ry = ((unsigned)yy < 128u);
            #pragma unroll
            for (int kx = 0; kx < 3; kx++) {
                int xx = x + kx - 1;
                in[ci*9 + ky*3 + kx] = (ry && ((unsigned)xx < 128u))
                    ? __ldg(&inp[(ci*128 + yy)*128 + xx]) : 0.0f;
            }
        }

    float4* F = (float4*)g_feat;
    #pragma unroll
    for (int c4 = 0; c4 < 16; c4++) {
        float4 acc = make_float4(sb[c4*4+0], sb[c4*4+1], sb[c4*4+2], sb[c4*4+3]);
        #pragma unroll
        for (int j = 0; j < 27; j++) {
            float fin = in[j];
            const float4 wv = *(const float4*)&sw[j*64 + c4*4];
            acc.x = fmaf(fin, wv.x, acc.x);
            acc.y = fmaf(fin, wv.y, acc.y);
            acc.z = fmaf(fin, wv.z, acc.z);
            acc.w = fmaf(fin, wv.w, acc.w);
        }
        F[t*16 + c4] = acc;
    }
}

// ---------------- Kernel 2: phase MLP, parallel (1 block, 1024 threads) ----------------
__global__ void __launch_bounds__(1024)
phase_mlp(const float* __restrict__ w1, const float* __restrict__ b1,
          const float* __restrict__ w2, const float* __restrict__ b2,
          const float* __restrict__ rw, const float* __restrict__ rb,
          const float* __restrict__ ow, const float* __restrict__ ob) {
    __shared__ float sw2[64*65];   // transposed-padded w2 [c][j], stride 65
    __shared__ float se1[16*64];
    __shared__ float se2[16*64];
    int t = threadIdx.x;
    for (int idx = t; idx < 4096; idx += 1024) {
        int c = idx >> 6, j = idx & 63;
        sw2[c*65 + j] = __ldg(&w2[idx]);
    }
    {
        int ph = t >> 6, c = t & 63;
        int py = ph >> 2, px = ph & 3;
        float ch = (py + 0.5f)/4.0f; ch = ch - floorf(ch + 0.001f) - 0.5f;
        float cw = (px + 0.5f)/4.0f; cw = cw - floorf(cw + 0.001f) - 0.5f;
        const float cs = 0.25f;
        float s = __ldg(&b1[c]);
        s = fmaf(__ldg(&w1[c*4+0]), cs, s);
        s = fmaf(__ldg(&w1[c*4+1]), cs, s);
        s = fmaf(__ldg(&w1[c*4+2]), ch, s);
        s = fmaf(__ldg(&w1[c*4+3]), cw, s);
        se1[ph*64 + c] = fmaxf(s, 0.0f);
    }
    __syncthreads();
    {
        int ph = t >> 6, c = t & 63;
        float s = __ldg(&b2[c]);
        #pragma unroll 8
        for (int j = 0; j < 64; j++)
            s = fmaf(sw2[c*65 + j], se1[ph*64 + j], s);
        se2[ph*64 + c] = fmaxf(s, 0.0f);
    }
    __syncthreads();
    if (t < 96) {
        int ph = t / 6, which = t % 6;
        if (which < 2) {
            float s = __ldg(&ob[which]);
            for (int j = 0; j < 64; j++)
                s = fmaf(__ldg(&ow[which*64 + j]), se2[ph*64 + j], s);
            g_off[ph*2 + which] = s;
        } else {
            int e = which - 2;
            float s = __ldg(&rb[e]);
            for (int j = 0; j < 64; j++)
                s = fmaf(__ldg(&rw[e*64 + j]), se2[ph*64 + j], s);
            g_r[ph*4 + e] = 1.0f/(1.0f + expf(-s));
        }
    }
}

// ---------------- Kernel 3: build A(r), B(r) per phase ----------------
__global__ void build_ab(const float* __restrict__ wc, const float* __restrict__ we) {
    int t = blockIdx.x*blockDim.x + threadIdx.x;   // 16384 threads
    if (t < 8192) {
        int ph = t >> 9, rem = t & 511;
        int c = rem >> 3, k = rem & 7;
        float s = 0.0f;
        #pragma unroll
        for (int e = 0; e < 4; e++)
            s = fmaf(g_r[ph*4+e], __ldg(&we[(e*64 + c)*8 + k]), s);
        g_A[ph*512 + c*8 + k] = s;
    } else {
        int u = t - 8192;
        int ph = u >> 9, rem = u & 511;
        int k = rem >> 6, c = rem & 63;
        float s = 0.0f;
        #pragma unroll
        for (int e = 0; e < 4; e++)
            s = fmaf(g_r[ph*4+e], __ldg(&wc[(e*8 + k)*64 + c]), s);
        g_B[ph*512 + k*64 + c] = s;
    }
}

// ---------------- Kernel 4: fused grid-sample + expert mixing (smem-staged) ----------------
// Block: 128 threads = one hi-res row segment (fixed y, x in [X0, X0+128)).
// Per phase ph (x&3): needs LR rows yc0/yc1 and LR x window [s(ph), s(ph)+33].
// Stage windows in smem in two 32-channel chunks; bilinear+GEMM from LDS.
#define C4STR 1188   // floats per c4-region: 8 phrow * 148 + 4 pad (1188 % 32 == 4)
__global__ void __launch_bounds__(128)
main_fused() {
    __shared__ __align__(16) float sF[8*C4STR];   // 38,016 B stage buffer
    __shared__ __align__(16) float sAB[4*520];    // 8,320 B  (B, then A)
    __shared__ float s_off0[4], s_wy0m[4], s_wy1m[4];
    __shared__ int   s_sx[4], s_yc[8];            // yc[ph*2 + row]

    int tid = threadIdx.x;
    int p0 = blockIdx.x << 7;
    int y  = p0 >> 9;
    int X0 = p0 & 511;
    int py4 = y & 3;

    if (tid < 4) {
        int ph = tid;
        float off0 = g_off[(py4*4+ph)*2+0];
        float off1 = g_off[(py4*4+ph)*2+1];
        s_off0[ph] = off0;
        float ys = ((float)y + 0.5f)*0.25f - 0.5f + off1;
        float y0f = floorf(ys);
        float wy1 = ys - y0f, wy0 = 1.0f - wy1;
        int y0 = (int)y0f, y1 = y0 + 1;
        s_wy0m[ph] = ((unsigned)y0 < 128u) ? wy0 : 0.0f;
        s_wy1m[ph] = ((unsigned)y1 < 128u) ? wy1 : 0.0f;
        s_yc[ph*2+0] = min(max(y0,0),127);
        s_yc[ph*2+1] = min(max(y1,0),127);
        float xs0 = ((float)X0 + 0.5f)*0.25f - 0.5f + off0;
        s_sx[ph] = (int)floorf(xs0);
    }
    // load B into sAB: [ph][k][c], per-phase stride 520 (== 8 mod 32)
    for (int i = tid; i < 2048; i += 128)
        sAB[(i>>9)*520 + (i&511)] = g_B[(py4*4 + (i>>9))*512 + (i&511)];
    __syncthreads();

    int x = X0 + tid;
    int ph = tid & 3;
    float xs = ((float)x + 0.5f)*0.25f - 0.5f + s_off0[ph];
    float x0f = floorf(xs);
    float wx1 = xs - x0f, wx0 = 1.0f - wx1;
    int x0 = (int)x0f, x1 = x0 + 1;
    float wx0m = ((unsigned)x0 < 128u) ? wx0 : 0.0f;
    float wx1m = ((unsigned)x1 < 128u) ? wx1 : 0.0f;
    float w00 = s_wy0m[ph]*wx0m, w01 = s_wy0m[ph]*wx1m;
    float w10 = s_wy1m[ph]*wx0m, w11 = s_wy1m[ph]*wx1m;
    int i0 = x0 - s_sx[ph];              // guaranteed 0..32 (floor-monotone)
    int sbase = ph*296 + i0*4;           // within a c4 region

    const float4* F4 = (const float4*)g_feat;
    float4 f4[16];
    float mid[8] = {0,0,0,0,0,0,0,0};

    #pragma unroll
    for (int cc = 0; cc < 2; cc++) {
        if (cc) __syncthreads();         // prev chunk compute done before overwrite
        // stage: 8 c4-lanes x 8 (ph,row) x 36 px, inner c4 -> coalesced 128B/px reads
        for (int idx = tid; idx < 2304; idx += 128) {
            int c4l = idx & 7;
            int rem = idx >> 3;
            int i   = rem % 36;
            int pr  = rem / 36;          // ph*2 + row
            int yr  = s_yc[pr];
            int xc  = min(max(s_sx[pr>>1] + i, 0), 127);
            ((float4*)(sF + c4l*C4STR + pr*148))[i] = F4[(yr*128 + xc)*16 + cc*8 + c4l];
        }
        __syncthreads();
        // compute: bilinear + accumulate mid = B * fea0
        #pragma unroll
        for (int c4l = 0; c4l < 8; c4l++) {
            const float* bp = sF + c4l*C4STR + sbase;
            float4 v00 = *(const float4*)(bp);
            float4 v01 = *(const float4*)(bp + 4);
            float4 v10 = *(const float4*)(bp + 148);
            float4 v11 = *(const float4*)(bp + 152);
            float4 r;
            r.x = fmaf(v11.x, w11, fmaf(v10.x, w10, fmaf(v01.x, w01, v00.x*w00)));
            r.y = fmaf(v11.y, w11, fmaf(v10.y, w10, fmaf(v01.y, w01, v00.y*w00)));
            r.z = fmaf(v11.z, w11, fmaf(v10.z, w10, fmaf(v01.z, w01, v00.z*w00)));
            r.w = fmaf(v11.w, w11, fmaf(v10.w, w10, fmaf(v01.w, w01, v00.w*w00)));
            f4[cc*8 + c4l] = r;
            const float4* B4 = (const float4*)(sAB + ph*520);
            #pragma unroll
            for (int k = 0; k < 8; k++) {
                float4 bv = B4[k*16 + cc*8 + c4l];
                mid[k] = fmaf(bv.x, r.x, fmaf(bv.y, r.y, fmaf(bv.z, r.z, fmaf(bv.w, r.w, mid[k]))));
            }
        }
    }
    __syncthreads();
    // load A into sAB (B no longer needed): [ph][c][k]
    for (int i = tid; i < 2048; i += 128)
        sAB[(i>>9)*520 + (i&511)] = g_A[(py4*4 + (i>>9))*512 + (i&511)];
    __syncthreads();

    int p = p0 + tid;
    const float4* A4 = (const float4*)(sAB + ph*520);
    #pragma unroll
    for (int c4 = 0; c4 < 16; c4++) {
        float4 fe = f4[c4];
        float fr[4] = {fe.x, fe.y, fe.z, fe.w};
        #pragma unroll
        for (int u = 0; u < 4; u++) {
            int c = c4*4 + u;
            float4 a0 = A4[c*2], a1 = A4[c*2+1];
            float s = fr[u];
            s = fmaf(a0.x, mid[0], s);
            s = fmaf(a0.y, mid[1], s);
            s = fmaf(a0.z, mid[2], s);
            s = fmaf(a0.w, mid[3], s);
            s = fmaf(a1.x, mid[4], s);
            s = fmaf(a1.y, mid[5], s);
            s = fmaf(a1.z, mid[6], s);
            s = fmaf(a1.w, mid[7], s);
            g_hidden[c*NPIX + p] = s;
        }
    }
}

// ---------------- Kernel 5: tail conv3x3 (64 -> 3, 512x512), smem-tiled ----------------
__global__ void __launch_bounds__(128)
tail_conv(const float* __restrict__ tw, const float* __restrict__ tb) {
    __shared__ float sh[4*10*72];    // [cc][row 0..9][i 0..71], i = x - X0 + 4
    __shared__ float swc[4*27];      // [cc][o][9]

    int bx = blockIdx.x & 7, by = blockIdx.x >> 3;
    int X0 = bx*64, Y0 = by*8;
    int lx = (threadIdx.x & 15)*4;
    int ly = threadIdx.x >> 4;

    float4 acc[3];
    #pragma unroll
    for (int o = 0; o < 3; o++) {
        float bo = __ldg(&tb[o]);
        acc[o] = make_float4(bo, bo, bo, bo);
    }

    for (int ch = 0; ch < 64; ch += 4) {
        __syncthreads();
        for (int idx = threadIdx.x; idx < 4*10*18; idx += 128) {
            int q  = idx % 18;
            int r  = (idx / 18) % 10;
            int cc = idx / 180;
            int gy  = Y0 - 1 + r;
            int gx4 = X0 - 4 + q*4;
            float4 v = make_float4(0.f, 0.f, 0.f, 0.f);
            if ((unsigned)gy < 512u && (unsigned)gx4 < 512u)
                v = *(const float4*)&g_hidden[(ch+cc)*NPIX + gy*512 + gx4];
            *(float4*)&sh[(cc*10 + r)*72 + q*4] = v;
        }
        for (int idx = threadIdx.x; idx < 108; idx += 128) {
            int cc = idx / 27, rem = idx % 27, o = rem / 9, k = rem % 9;
            swc[idx] = __ldg(&tw[(o*64 + ch + cc)*9 + k]);
        }
        __syncthreads();

        #pragma unroll
        for (int cc = 0; cc < 4; cc++) {
            float v[3][6];
            #pragma unroll
            for (int r = 0; r < 3; r++) {
                const float* row = &sh[(cc*10 + ly + r)*72];
                float4 a = *(const float4*)&row[lx];
                float4 b = *(const float4*)&row[lx+4];
                float4 c = *(const float4*)&row[lx+8];
                v[r][0]=a.w; v[r][1]=b.x; v[r][2]=b.y;
                v[r][3]=b.z; v[r][4]=b.w; v[r][5]=c.x;
            }
            #pragma unroll
            for (int o = 0; o < 3; o++) {
                const float* wp = &swc[cc*27 + o*9];
                #pragma unroll
                for (int ry = 0; ry < 3; ry++)
                    #pragma unroll
                    for (int dx = 0; dx < 3; dx++) {
                        float wv = wp[ry*3+dx];
                        acc[o].x = fmaf(v[ry][0+dx], wv, acc[o].x);
                        acc[o].y = fmaf(v[ry][1+dx], wv, acc[o].y);
                        acc[o].z = fmaf(v[ry][2+dx], wv, acc[o].z);
                        acc[o].w = fmaf(v[ry][3+dx], wv, acc[o].w);
                    }
            }
        }
    }
    int base = (Y0+ly)*512 + X0 + lx;
    #pragma unroll
    for (int o = 0; o < 3; o++)
        *(float4*)&g_pred[o*NPIX + base] = acc[o];
}

// ---------------- Kernel 6: query gather (nearest, round-half-even) ----------------
__global__ void gather_q(const float* __restrict__ coord,
                         const float* __restrict__ cell,
                         float* __restrict__ out) {
    int q = blockIdx.x*blockDim.x + threadIdx.x;
    if (q >= NQ) return;
    float cy = __ldg(&coord[q*2+0]);
    float cx = __ldg(&coord[q*2+1]);
    float ly = __ldg(&cell[q*2+0]);
    float lx = __ldg(&cell[q*2+1]);
    float gyq = fminf(fmaxf(cy - ly*0.5f + 1e-6f, -1.0f + 1e-6f), 1.0f - 1e-6f);
    float gxq = fminf(fmaxf(cx - lx*0.5f + 1e-6f, -1.0f + 1e-6f), 1.0f - 1e-6f);
    int xi = (int)rintf((gxq + 1.0f)*0.5f*511.0f);
    int yi = (int)rintf((gyq + 1.0f)*0.5f*511.0f);
    xi = min(max(xi,0),511);
    yi = min(max(yi,0),511);
    int idx = (yi << 9) + xi;
    out[q*3+0] = g_pred[idx];
    out[q*3+1] = g_pred[NPIX + idx];
    out[q*3+2] = g_pred[2*NPIX + idx];
}

extern "C" void kernel_launch(void* const* d_in, const int* in_sizes, int n_in,
                              void* d_out, int out_size) {
    const float* inp    = (const float*)d_in[0];
    const float* coord  = (const float*)d_in[1];
    const float* cell   = (const float*)d_in[2];
    const float* enc_w  = (const float*)d_in[3];
    const float* enc_b  = (const float*)d_in[4];
    const float* body_w1= (const float*)d_in[5];
    const float* body_b1= (const float*)d_in[6];
    const float* body_w2= (const float*)d_in[7];
    const float* body_b2= (const float*)d_in[8];
    const float* rout_w = (const float*)d_in[9];
    const float* rout_b = (const float*)d_in[10];
    const float* off_w  = (const float*)d_in[11];
    const float* off_b  = (const float*)d_in[12];
    const float* tail_w = (const float*)d_in[13];
    const float* tail_b = (const float*)d_in[14];
    const float* wcmp   = (const float*)d_in[15];
    const float* wexp   = (const float*)d_in[16];
    float* out = (float*)d_out;

    enc_conv<<<128, 128>>>(inp, enc_w, enc_b);
    phase_mlp<<<1, 1024>>>(body_w1, body_b1, body_w2, body_b2,
                           rout_w, rout_b, off_w, off_b);
    build_ab<<<32, 512>>>(wcmp, wexp);
    main_fused<<<2048, 128>>>();
    tail_conv<<<512, 128>>>(tail_w, tail_b);
    gather_q<<<1024, 256>>>(coord, cell, out);
}

// round 4
// speedup vs baseline: 1.1851x; 1.1851x over previous
#include <cuda_runtime.h>
#include <cuda_bf16.h>

#define HLR 128
#define WLR 128
#define HH 512
#define WH 512
#define CC 64
#define NPIX (HH*WH)      // 262144
#define NQ 262144

typedef unsigned long long ull;

// ---- packed f32x2 helpers (sm_100+: fma.rn.f32x2 -> FFMA2) ----
__device__ __forceinline__ ull pk2(float lo, float hi) {
    ull r; asm("mov.b64 %0, {%1, %2};" : "=l"(r) : "f"(lo), "f"(hi)); return r;
}
__device__ __forceinline__ void upk2(ull v, float& lo, float& hi) {
    asm("mov.b64 {%0, %1}, %2;" : "=f"(lo), "=f"(hi) : "l"(v));
}
__device__ __forceinline__ ull fma2(ull a, ull b, ull c) {
    ull d; asm("fma.rn.f32x2 %0, %1, %2, %3;" : "=l"(d) : "l"(a), "l"(b), "l"(c)); return d;
}
__device__ __forceinline__ ull mul2(ull a, ull b) {
    ull d; asm("mul.rn.f32x2 %0, %1, %2;" : "=l"(d) : "l"(a), "l"(b)); return d;
}

// ---- scratch (device globals: allocation-free) ----
__device__ __align__(16) float g_feat[CC*HLR*WLR];   // 4 MB, channel-FIRST [c][y][x]
__device__ __align__(16) float g_hidden[CC*NPIX];    // 64 MB, channel-FIRST [c][y][x]
__device__ __align__(16) float g_pred[3*NPIX];       // 3 MB  [o][y][x]
__device__ float g_off[16*2];
__device__ float g_r[16*4];
__device__ float g_A[16*512];            // [ph][c][k]  (64x8)
__device__ float g_B[16*512];            // [ph][k][c]  (8x64)

// ---------------- Kernel 1: encoder conv3x3 (3 -> 64, 128x128) -> channel-first ----------------
__global__ void __launch_bounds__(128)
enc_conv(const float* __restrict__ inp,
         const float* __restrict__ w,
         const float* __restrict__ b) {
    __shared__ float sw[27*64];   // [j][c]
    __shared__ float sb[64];
    for (int idx = threadIdx.x; idx < 27*64; idx += 128) {
        int j = idx >> 6, c = idx & 63;
        sw[idx] = __ldg(&w[c*27 + j]);
    }
    if (threadIdx.x < 64) sb[threadIdx.x] = __ldg(&b[threadIdx.x]);
    __syncthreads();

    int t = blockIdx.x*128 + threadIdx.x;   // pixel
    int x = t & 127, y = t >> 7;

    float in[27];
    #pragma unroll
    for (int ci = 0; ci < 3; ci++)
        #pragma unroll
        for (int ky = 0; ky < 3; ky++) {
            int yy = y + ky - 1;
            bool ry = ((unsigned)yy < 128u);
            #pragma unroll
            for (int kx = 0; kx < 3; kx++) {
                int xx = x + kx - 1;
                in[ci*9 + ky*3 + kx] = (ry && ((unsigned)xx < 128u))
                    ? __ldg(&inp[(ci*128 + yy)*128 + xx]) : 0.0f;
            }
        }

    #pragma unroll
    for (int c4 = 0; c4 < 16; c4++) {
        float4 acc = make_float4(sb[c4*4+0], sb[c4*4+1], sb[c4*4+2], sb[c4*4+3]);
        #pragma unroll
        for (int j = 0; j < 27; j++) {
            float fin = in[j];
            const float4 wv = *(const float4*)&sw[j*64 + c4*4];
            acc.x = fmaf(fin, wv.x, acc.x);
            acc.y = fmaf(fin, wv.y, acc.y);
            acc.z = fmaf(fin, wv.z, acc.z);
            acc.w = fmaf(fin, wv.w, acc.w);
        }
        g_feat[(c4*4+0)*16384 + t] = acc.x;
        g_feat[(c4*4+1)*16384 + t] = acc.y;
        g_feat[(c4*4+2)*16384 + t] = acc.z;
        g_feat[(c4*4+3)*16384 + t] = acc.w;
    }
}

// ---------------- Kernel 2: phase MLP, parallel (1 block, 1024 threads) ----------------
__global__ void __launch_bounds__(1024)
phase_mlp(const float* __restrict__ w1, const float* __restrict__ b1,
          const float* __restrict__ w2, const float* __restrict__ b2,
          const float* __restrict__ rw, const float* __restrict__ rb,
          const float* __restrict__ ow, const float* __restrict__ ob) {
    __shared__ float sw2[64*65];
    __shared__ float se1[16*64];
    __shared__ float se2[16*64];
    int t = threadIdx.x;
    for (int idx = t; idx < 4096; idx += 1024) {
        int c = idx >> 6, j = idx & 63;
        sw2[c*65 + j] = __ldg(&w2[idx]);
    }
    {
        int ph = t >> 6, c = t & 63;
        int py = ph >> 2, px = ph & 3;
        float ch = (py + 0.5f)/4.0f; ch = ch - floorf(ch + 0.001f) - 0.5f;
        float cw = (px + 0.5f)/4.0f; cw = cw - floorf(cw + 0.001f) - 0.5f;
        const float cs = 0.25f;
        float s = __ldg(&b1[c]);
        s = fmaf(__ldg(&w1[c*4+0]), cs, s);
        s = fmaf(__ldg(&w1[c*4+1]), cs, s);
        s = fmaf(__ldg(&w1[c*4+2]), ch, s);
        s = fmaf(__ldg(&w1[c*4+3]), cw, s);
        se1[ph*64 + c] = fmaxf(s, 0.0f);
    }
    __syncthreads();
    {
        int ph = t >> 6, c = t & 63;
        float s = __ldg(&b2[c]);
        #pragma unroll 8
        for (int j = 0; j < 64; j++)
            s = fmaf(sw2[c*65 + j], se1[ph*64 + j], s);
        se2[ph*64 + c] = fmaxf(s, 0.0f);
    }
    __syncthreads();
    if (t < 96) {
        int ph = t / 6, which = t % 6;
        if (which < 2) {
            float s = __ldg(&ob[which]);
            for (int j = 0; j < 64; j++)
                s = fmaf(__ldg(&ow[which*64 + j]), se2[ph*64 + j], s);
            g_off[ph*2 + which] = s;
        } else {
            int e = which - 2;
            float s = __ldg(&rb[e]);
            for (int j = 0; j < 64; j++)
                s = fmaf(__ldg(&rw[e*64 + j]), se2[ph*64 + j], s);
            g_r[ph*4 + e] = 1.0f/(1.0f + expf(-s));
        }
    }
}

// ---------------- Kernel 3: build A(r), B(r) per phase ----------------
__global__ void build_ab(const float* __restrict__ wc, const float* __restrict__ we) {
    int t = blockIdx.x*blockDim.x + threadIdx.x;   // 16384 threads
    if (t < 8192) {
        int ph = t >> 9, rem = t & 511;
        int c = rem >> 3, k = rem & 7;
        float s = 0.0f;
        #pragma unroll
        for (int e = 0; e < 4; e++)
            s = fmaf(g_r[ph*4+e], __ldg(&we[(e*64 + c)*8 + k]), s);
        g_A[ph*512 + c*8 + k] = s;
    } else {
        int u = t - 8192;
        int ph = u >> 9, rem = u & 511;
        int k = rem >> 6, c = rem & 63;
        float s = 0.0f;
        #pragma unroll
        for (int e = 0; e < 4; e++)
            s = fmaf(g_r[ph*4+e], __ldg(&wc[(e*8 + k)*64 + c]), s);
        g_B[ph*512 + k*64 + c] = s;
    }
}

// ---------------- Kernel 4: fused grid-sample + expert mixing ----------------
// Block: 128 threads, one HR row segment. Warp w handles phase w: x = X0 + 4*lane + w.
// xs increments exactly 1.0 per lane -> x0 lane-consecutive -> coalesced corner loads.
__global__ void __launch_bounds__(128)
main_fused() {
    __shared__ __align__(16) float sB[4*520];   // [phl][k*64+c], stride 520
    __shared__ __align__(16) float sA[4*520];   // [phl][c*8+k]

    int tid = threadIdx.x;
    int p0 = blockIdx.x << 7;
    int y  = p0 >> 9;
    int X0 = p0 & 511;
    int py4 = y & 3;

    for (int i = tid; i < 2048; i += 128) {
        int phl = i >> 9, ii = i & 511;
        sB[phl*520 + ii] = g_B[(py4*4 + phl)*512 + ii];
        sA[phl*520 + ii] = g_A[(py4*4 + phl)*512 + ii];
    }
    __syncthreads();

    int w    = tid >> 5;
    int lane = tid & 31;
    int x = X0 + 4*lane + w;
    int p = (y << 9) + x;
    int ph = py4*4 + w;

    float off0 = g_off[ph*2+0];
    float off1 = g_off[ph*2+1];

    float xs = ((float)x + 0.5f)*0.25f - 0.5f + off0;
    float ys = ((float)y + 0.5f)*0.25f - 0.5f + off1;
    float x0f = floorf(xs), y0f = floorf(ys);
    float wx1 = xs - x0f, wx0 = 1.0f - wx1;
    float wy1 = ys - y0f, wy0 = 1.0f - wy1;
    int x0 = (int)x0f, y0 = (int)y0f;
    int x1 = x0 + 1, y1 = y0 + 1;
    float mx0 = ((unsigned)x0 < 128u) ? 1.0f : 0.0f;
    float mx1 = ((unsigned)x1 < 128u) ? 1.0f : 0.0f;
    float my0 = ((unsigned)y0 < 128u) ? 1.0f : 0.0f;
    float my1 = ((unsigned)y1 < 128u) ? 1.0f : 0.0f;
    float w00 = wy0*wx0*my0*mx0;
    float w01 = wy0*wx1*my0*mx1;
    float w10 = wy1*wx0*my1*mx0;
    float w11 = wy1*wx1*my1*mx1;
    int xc0 = min(max(x0,0),127), xc1 = min(max(x1,0),127);
    int yc0 = min(max(y0,0),127), yc1 = min(max(y1,0),127);
    int i00 = yc0*128 + xc0, i01 = yc0*128 + xc1;
    int i10 = yc1*128 + xc0, i11 = yc1*128 + xc1;

    ull W00 = pk2(w00,w00), W01 = pk2(w01,w01);
    ull W10 = pk2(w10,w10), W11 = pk2(w11,w11);

    // bilinear: channel pairs, coalesced scalar loads
    ull f2[32];
    #pragma unroll
    for (int c2 = 0; c2 < 32; c2++) {
        const float* fa = g_feat + (2*c2)*16384;
        const float* fb = fa + 16384;
        ull v00 = pk2(__ldg(fa + i00), __ldg(fb + i00));
        ull v01 = pk2(__ldg(fa + i01), __ldg(fb + i01));
        ull v10 = pk2(__ldg(fa + i10), __ldg(fb + i10));
        ull v11 = pk2(__ldg(fa + i11), __ldg(fb + i11));
        f2[c2] = fma2(v11, W11, fma2(v10, W10, fma2(v01, W01, mul2(v00, W00))));
    }

    // mid = B * fea0  (8x64), c-packed
    float mid[8];
    {
        const ulonglong2* B4 = (const ulonglong2*)(sB + w*520);
        #pragma unroll
        for (int k = 0; k < 8; k++) {
            ull acc = 0ULL;
            #pragma unroll
            for (int j = 0; j < 16; j++) {
                ulonglong2 bb = B4[k*16 + j];
                acc = fma2(bb.x, f2[2*j+0], acc);
                acc = fma2(bb.y, f2[2*j+1], acc);
            }
            float lo, hi; upk2(acc, lo, hi);
            mid[k] = lo + hi;
        }
    }
    ull m2[4];
    #pragma unroll
    for (int k2 = 0; k2 < 4; k2++) m2[k2] = pk2(mid[2*k2], mid[2*k2+1]);

    // hidden = fea0 + A * mid  (64x8), k-packed, store stride-4 (merged by peer warps)
    #pragma unroll
    for (int c2 = 0; c2 < 32; c2++) {
        float flo, fhi; upk2(f2[c2], flo, fhi);
        const ulonglong2* A4 = (const ulonglong2*)(sA + w*520 + (2*c2)*8);
        ulonglong2 qa = A4[0], qb = A4[1];
        ull s = fma2(qa.x, m2[0], pk2(flo, 0.0f));
        s = fma2(qa.y, m2[1], s);
        s = fma2(qb.x, m2[2], s);
        s = fma2(qb.y, m2[3], s);
        float slo, shi; upk2(s, slo, shi);
        g_hidden[(2*c2)*NPIX + p] = slo + shi;
        ulonglong2 ra = A4[2], rb = A4[3];
        ull t = fma2(ra.x, m2[0], pk2(fhi, 0.0f));
        t = fma2(ra.y, m2[1], t);
        t = fma2(rb.x, m2[2], t);
        t = fma2(rb.y, m2[3], t);
        float tlo, thi; upk2(t, tlo, thi);
        g_hidden[(2*c2+1)*NPIX + p] = tlo + thi;
    }
}

// ---------------- Kernel 5: tail conv3x3 (64 -> 3, 512x512), smem-tiled ----------------
__global__ void __launch_bounds__(128)
tail_conv(const float* __restrict__ tw, const float* __restrict__ tb) {
    __shared__ float sh[4*10*72];
    __shared__ float swc[4*27];

    int bx = blockIdx.x & 7, by = blockIdx.x >> 3;
    int X0 = bx*64, Y0 = by*8;
    int lx = (threadIdx.x & 15)*4;
    int ly = threadIdx.x >> 4;

    float4 acc[3];
    #pragma unroll
    for (int o = 0; o < 3; o++) {
        float bo = __ldg(&tb[o]);
        acc[o] = make_float4(bo, bo, bo, bo);
    }

    for (int ch = 0; ch < 64; ch += 4) {
        __syncthreads();
        for (int idx = threadIdx.x; idx < 4*10*18; idx += 128) {
            int q  = idx % 18;
            int r  = (idx / 18) % 10;
            int cc = idx / 180;
            int gy  = Y0 - 1 + r;
            int gx4 = X0 - 4 + q*4;
            float4 v = make_float4(0.f, 0.f, 0.f, 0.f);
            if ((unsigned)gy < 512u && (unsigned)gx4 < 512u)
                v = *(const float4*)&g_hidden[(ch+cc)*NPIX + gy*512 + gx4];
            *(float4*)&sh[(cc*10 + r)*72 + q*4] = v;
        }
        for (int idx = threadIdx.x; idx < 108; idx += 128) {
            int cc = idx / 27, rem = idx % 27, o = rem / 9, k = rem % 9;
            swc[idx] = __ldg(&tw[(o*64 + ch + cc)*9 + k]);
        }
        __syncthreads();

        #pragma unroll
        for (int cc = 0; cc < 4; cc++) {
            float v[3][6];
            #pragma unroll
            for (int r = 0; r < 3; r++) {
                const float* row = &sh[(cc*10 + ly + r)*72];
                float4 a = *(const float4*)&row[lx];
                float4 b = *(const float4*)&row[lx+4];
                float4 c = *(const float4*)&row[lx+8];
                v[r][0]=a.w; v[r][1]=b.x; v[r][2]=b.y;
                v[r][3]=b.z; v[r][4]=b.w; v[r][5]=c.x;
            }
            #pragma unroll
            for (int o = 0; o < 3; o++) {
                const float* wp = &swc[cc*27 + o*9];
                #pragma unroll
                for (int ry = 0; ry < 3; ry++)
                    #pragma unroll
                    for (int dx = 0; dx < 3; dx++) {
                        float wv = wp[ry*3+dx];
                        acc[o].x = fmaf(v[ry][0+dx], wv, acc[o].x);
                        acc[o].y = fmaf(v[ry][1+dx], wv, acc[o].y);
                        acc[o].z = fmaf(v[ry][2+dx], wv, acc[o].z);
                        acc[o].w = fmaf(v[ry][3+dx], wv, acc[o].w);
                    }
            }
        }
    }
    int base = (Y0+ly)*512 + X0 + lx;
    #pragma unroll
    for (int o = 0; o < 3; o++)
        *(float4*)&g_pred[o*NPIX + base] = acc[o];
}

// ---------------- Kernel 6: query gather (nearest, round-half-even) ----------------
__global__ void gather_q(const float* __restrict__ coord,
                         const float* __restrict__ cell,
                         float* __restrict__ out) {
    int q = blockIdx.x*blockDim.x + threadIdx.x;
    if (q >= NQ) return;
    float cy = __ldg(&coord[q*2+0]);
    float cx = __ldg(&coord[q*2+1]);
    float ly = __ldg(&cell[q*2+0]);
    float lx = __ldg(&cell[q*2+1]);
    float gyq = fminf(fmaxf(cy - ly*0.5f + 1e-6f, -1.0f + 1e-6f), 1.0f - 1e-6f);
    float gxq = fminf(fmaxf(cx - lx*0.5f + 1e-6f, -1.0f + 1e-6f), 1.0f - 1e-6f);
    int xi = (int)rintf((gxq + 1.0f)*0.5f*511.0f);
    int yi = (int)rintf((gyq + 1.0f)*0.5f*511.0f);
    xi = min(max(xi,0),511);
    yi = min(max(yi,0),511);
    int idx = (yi << 9) + xi;
    out[q*3+0] = g_pred[idx];
    out[q*3+1] = g_pred[NPIX + idx];
    out[q*3+2] = g_pred[2*NPIX + idx];
}

extern "C" void kernel_launch(void* const* d_in, const int* in_sizes, int n_in,
                              void* d_out, int out_size) {
    const float* inp    = (const float*)d_in[0];
    const float* coord  = (const float*)d_in[1];
    const float* cell   = (const float*)d_in[2];
    const float* enc_w  = (const float*)d_in[3];
    const float* enc_b  = (const float*)d_in[4];
    const float* body_w1= (const float*)d_in[5];
    const float* body_b1= (const float*)d_in[6];
    const float* body_w2= (const float*)d_in[7];
    const float* body_b2= (const float*)d_in[8];
    const float* rout_w = (const float*)d_in[9];
    const float* rout_b = (const float*)d_in[10];
    const float* off_w  = (const float*)d_in[11];
    const float* off_b  = (const float*)d_in[12];
    const float* tail_w = (const float*)d_in[13];
    const float* tail_b = (const float*)d_in[14];
    const float* wcmp   = (const float*)d_in[15];
    const float* wexp   = (const float*)d_in[16];
    float* out = (float*)d_out;

    enc_conv<<<128, 128>>>(inp, enc_w, enc_b);
    phase_mlp<<<1, 1024>>>(body_w1, body_b1, body_w2, body_b2,
                           rout_w, rout_b, off_w, off_b);
    build_ab<<<32, 512>>>(wcmp, wexp);
    main_fused<<<2048, 128>>>();
    tail_conv<<<512, 128>>>(tail_w, tail_b);
    gather_q<<<1024, 256>>>(coord, cell, out);
}

// round 5
// speedup vs baseline: 1.3641x; 1.1511x over previous
#include <cuda_runtime.h>
#include <cuda_bf16.h>

#define HLR 128
#define WLR 128
#define HH 512
#define WH 512
#define CC 64
#define NPIX (HH*WH)      // 262144
#define NQ 262144

typedef unsigned long long ull;

// ---- packed f32x2 helpers (sm_103a: fma.rn.f32x2 -> FFMA2) ----
__device__ __forceinline__ ull pk2(float lo, float hi) {
    ull r; asm("mov.b64 %0, {%1, %2};" : "=l"(r) : "f"(lo), "f"(hi)); return r;
}
__device__ __forceinline__ void upk2(ull v, float& lo, float& hi) {
    asm("mov.b64 {%0, %1}, %2;" : "=f"(lo), "=f"(hi) : "l"(v));
}
__device__ __forceinline__ ull fma2(ull a, ull b, ull c) {
    ull d; asm("fma.rn.f32x2 %0, %1, %2, %3;" : "=l"(d) : "l"(a), "l"(b), "l"(c)); return d;
}
__device__ __forceinline__ ull mul2(ull a, ull b) {
    ull d; asm("mul.rn.f32x2 %0, %1, %2;" : "=l"(d) : "l"(a), "l"(b)); return d;
}

// ---- scratch (device globals: allocation-free) ----
// g_feat2: channel-pair planes [c2][pix], each ull = (ch 2*c2, ch 2*c2+1)
__device__ __align__(16) ull g_feat2[32*HLR*WLR];            // 4 MB
// g_hidden2: channel-pair planes, PHASE-PERMUTED pixels: [c2][y*512 + w*128 + g]
// where x = 4*g + w
__device__ __align__(16) ull g_hidden2[32*NPIX];             // 64 MB
__device__ __align__(16) float4 g_pred4[NPIX];               // 4 MB [pix]{o0,o1,o2,-}
__device__ float g_off[16*2];
__device__ float g_r[16*4];
__device__ __align__(16) float g_A[16*512];      // [ph][c*8+k]
__device__ __align__(16) float g_B[16*512];      // [ph][k*64+c]

// ============ Kernel 1: encoder conv3x3 (blocks 0..511) + phase MLP (block 512) ============
__global__ void __launch_bounds__(256)
k_enc_phase(const float* __restrict__ inp,
            const float* __restrict__ ew, const float* __restrict__ eb,
            const float* __restrict__ w1, const float* __restrict__ b1,
            const float* __restrict__ w2, const float* __restrict__ b2,
            const float* __restrict__ rw, const float* __restrict__ rb,
            const float* __restrict__ ow, const float* __restrict__ ob) {
    __shared__ float sw[27*64];    // enc weights [j][c]
    __shared__ float sb[64];
    __shared__ float sw2[64*65];   // mlp w2 transposed-padded
    __shared__ float se1[1024];
    __shared__ float se2[1024];
    int t = threadIdx.x;

    if (blockIdx.x < 512) {
        // ---- encoder: 32 pixels per block, 8 channel-groups of 8 channels ----
        for (int idx = t; idx < 27*64; idx += 256) {
            int j = idx >> 6, c = idx & 63;
            sw[idx] = __ldg(&ew[c*27 + j]);
        }
        if (t < 64) sb[t] = __ldg(&eb[t]);
        __syncthreads();

        int px = blockIdx.x*32 + (t & 31);
        int grp = t >> 5;                       // 0..7 -> c4 in {2g, 2g+1}
        int x = px & 127, y = px >> 7;

        float in[27];
        #pragma unroll
        for (int ci = 0; ci < 3; ci++)
            #pragma unroll
            for (int ky = 0; ky < 3; ky++) {
                int yy = y + ky - 1;
                bool ry = ((unsigned)yy < 128u);
                #pragma unroll
                for (int kx = 0; kx < 3; kx++) {
                    int xx = x + kx - 1;
                    in[ci*9 + ky*3 + kx] = (ry && ((unsigned)xx < 128u))
                        ? __ldg(&inp[(ci*128 + yy)*128 + xx]) : 0.0f;
                }
            }
        #pragma unroll
        for (int u = 0; u < 2; u++) {
            int c4 = grp*2 + u;
            float4 acc = make_float4(sb[c4*4+0], sb[c4*4+1], sb[c4*4+2], sb[c4*4+3]);
            #pragma unroll
            for (int j = 0; j < 27; j++) {
                float fin = in[j];
                const float4 wv = *(const float4*)&sw[j*64 + c4*4];
                acc.x = fmaf(fin, wv.x, acc.x);
                acc.y = fmaf(fin, wv.y, acc.y);
                acc.z = fmaf(fin, wv.z, acc.z);
                acc.w = fmaf(fin, wv.w, acc.w);
            }
            g_feat2[(c4*2+0)*16384 + px] = pk2(acc.x, acc.y);
            g_feat2[(c4*2+1)*16384 + px] = pk2(acc.z, acc.w);
        }
    } else {
        // ---- phase MLP: 16 phases x 64 channels, 256 threads ----
        for (int idx = t; idx < 4096; idx += 256) {
            int c = idx >> 6, j = idx & 63;
            sw2[c*65 + j] = __ldg(&w2[idx]);
        }
        #pragma unroll
        for (int it = 0; it < 4; it++) {
            int item = t + it*256;
            int ph = item >> 6, c = item & 63;
            int py = ph >> 2, px = ph & 3;
            float ch = (py + 0.5f)/4.0f; ch = ch - floorf(ch + 0.001f) - 0.5f;
            float cw = (px + 0.5f)/4.0f; cw = cw - floorf(cw + 0.001f) - 0.5f;
            const float cs = 0.25f;
            float s = __ldg(&b1[c]);
            s = fmaf(__ldg(&w1[c*4+0]), cs, s);
            s = fmaf(__ldg(&w1[c*4+1]), cs, s);
            s = fmaf(__ldg(&w1[c*4+2]), ch, s);
            s = fmaf(__ldg(&w1[c*4+3]), cw, s);
            se1[item] = fmaxf(s, 0.0f);
        }
        __syncthreads();
        #pragma unroll
        for (int it = 0; it < 4; it++) {
            int item = t + it*256;
            int ph = item >> 6, c = item & 63;
            float s = __ldg(&b2[c]);
            #pragma unroll 8
            for (int j = 0; j < 64; j++)
                s = fmaf(sw2[c*65 + j], se1[ph*64 + j], s);
            se2[item] = fmaxf(s, 0.0f);
        }
        __syncthreads();
        if (t < 96) {
            int ph = t / 6, which = t % 6;
            if (which < 2) {
                float s = __ldg(&ob[which]);
                for (int j = 0; j < 64; j++)
                    s = fmaf(__ldg(&ow[which*64 + j]), se2[ph*64 + j], s);
                g_off[ph*2 + which] = s;
            } else {
                int e = which - 2;
                float s = __ldg(&rb[e]);
                for (int j = 0; j < 64; j++)
                    s = fmaf(__ldg(&rw[e*64 + j]), se2[ph*64 + j], s);
                g_r[ph*4 + e] = 1.0f/(1.0f + expf(-s));
            }
        }
    }
}

// ============ Kernel 2: build A(r), B(r) per phase ============
__global__ void build_ab(const float* __restrict__ wc, const float* __restrict__ we) {
    int t = blockIdx.x*blockDim.x + threadIdx.x;
    if (t < 8192) {
        int ph = t >> 9, rem = t & 511;
        int c = rem >> 3, k = rem & 7;
        float s = 0.0f;
        #pragma unroll
        for (int e = 0; e < 4; e++)
            s = fmaf(g_r[ph*4+e], __ldg(&we[(e*64 + c)*8 + k]), s);
        g_A[ph*512 + c*8 + k] = s;
    } else {
        int u = t - 8192;
        int ph = u >> 9, rem = u & 511;
        int k = rem >> 6, c = rem & 63;
        float s = 0.0f;
        #pragma unroll
        for (int e = 0; e < 4; e++)
            s = fmaf(g_r[ph*4+e], __ldg(&wc[(e*8 + k)*64 + c]), s);
        g_B[ph*512 + k*64 + c] = s;
    }
}

// ============ Kernel 3: fused grid-sample + expert mixing (2-pass, low-reg) ============
// Warp w handles phase w: x = X0 + 4*lane + w -> lane-consecutive LR sampling.
// Pass A: bilinear + mid = B*fea0 (fea0 discarded). Pass B: recompute bilinear (L1-hot),
// hidden = fea0 + A*mid, store to phase-permuted pair planes.
__global__ void __launch_bounds__(128)
main_fused() {
    __shared__ ull sBt[4*264];   // [phl][c2*8+k] = (B[k][2c2], B[k][2c2+1])
    __shared__ ull sAt[4*264];   // [phl][c2*8+k] = (A[2c2][k], A[2c2+1][k])

    int tid = threadIdx.x;
    int p0 = blockIdx.x << 7;
    int y  = p0 >> 9;
    int X0 = p0 & 511;
    int py4 = y & 3;

    const ull* GB = (const ull*)g_B;
    for (int i = tid; i < 1024; i += 128) {
        int phl = i >> 8, ii = i & 255;          // ii = c2*8 + k
        int c2 = ii >> 3, k = ii & 7;
        int ph = py4*4 + phl;
        sBt[phl*264 + ii] = GB[ph*256 + k*32 + c2];
        sAt[phl*264 + ii] = pk2(g_A[ph*512 + (2*c2)*8 + k],
                                g_A[ph*512 + (2*c2+1)*8 + k]);
    }
    __syncthreads();

    int w    = tid >> 5;
    int lane = tid & 31;
    int x = X0 + 4*lane + w;
    int ph = py4*4 + w;

    float off0 = g_off[ph*2+0];
    float off1 = g_off[ph*2+1];

    float xs = ((float)x + 0.5f)*0.25f - 0.5f + off0;
    float ys = ((float)y + 0.5f)*0.25f - 0.5f + off1;
    float x0f = floorf(xs), y0f = floorf(ys);
    float wx1 = xs - x0f, wx0 = 1.0f - wx1;
    float wy1 = ys - y0f, wy0 = 1.0f - wy1;
    int x0 = (int)x0f, y0 = (int)y0f;
    int x1 = x0 + 1, y1 = y0 + 1;
    float mx0 = ((unsigned)x0 < 128u) ? 1.0f : 0.0f;
    float mx1 = ((unsigned)x1 < 128u) ? 1.0f : 0.0f;
    float my0 = ((unsigned)y0 < 128u) ? 1.0f : 0.0f;
    float my1 = ((unsigned)y1 < 128u) ? 1.0f : 0.0f;
    float w00 = wy0*wx0*my0*mx0;
    float w01 = wy0*wx1*my0*mx1;
    float w10 = wy1*wx0*my1*mx0;
    float w11 = wy1*wx1*my1*mx1;
    int xc0 = min(max(x0,0),127), xc1 = min(max(x1,0),127);
    int yc0 = min(max(y0,0),127), yc1 = min(max(y1,0),127);
    int i00 = yc0*128 + xc0, i01 = yc0*128 + xc1;
    int i10 = yc1*128 + xc0, i11 = yc1*128 + xc1;

    ull W00 = pk2(w00,w00), W01 = pk2(w01,w01);
    ull W10 = pk2(w10,w10), W11 = pk2(w11,w11);

    // ---- pass A: accumulate mid = B * fea0 ----
    ull acc[8] = {0,0,0,0,0,0,0,0};
    const ull* Bp = sBt + w*264;
    #pragma unroll
    for (int c2 = 0; c2 < 32; c2++) {
        const ull* fp = g_feat2 + c2*16384;
        ull f = fma2(__ldg(fp+i11), W11,
                fma2(__ldg(fp+i10), W10,
                fma2(__ldg(fp+i01), W01,
                mul2(__ldg(fp+i00), W00))));
        #pragma unroll
        for (int k = 0; k < 8; k++)
            acc[k] = fma2(Bp[c2*8 + k], f, acc[k]);
    }
    ull mdup[8];
    #pragma unroll
    for (int k = 0; k < 8; k++) {
        float lo, hi; upk2(acc[k], lo, hi);
        float s = lo + hi;
        mdup[k] = pk2(s, s);
    }

    // ---- pass B: hidden = fea0 + A*mid, store permuted ----
    int g = (X0 >> 2) + lane;
    ull* H = g_hidden2 + ((y << 9) + (w << 7) + g);
    const ull* Ap = sAt + w*264;
    #pragma unroll
    for (int c2 = 31; c2 >= 0; c2--) {
        const ull* fp = g_feat2 + c2*16384;
        ull h = fma2(__ldg(fp+i11), W11,
                fma2(__ldg(fp+i10), W10,
                fma2(__ldg(fp+i01), W01,
                mul2(__ldg(fp+i00), W00))));
        #pragma unroll
        for (int k = 0; k < 8; k++)
            h = fma2(Ap[c2*8 + k], mdup[k], h);
        H[c2*NPIX] = h;
    }
}

// ============ Kernel 4: tail conv3x3 (64 -> 3), f32x2, permuted-input, float4 out ============
__global__ void __launch_bounds__(128)
tail_conv(const float* __restrict__ tw, const float* __restrict__ tb) {
    __shared__ float sh[4][4][10][19];   // [w][cc][row][j], x = X0-4 + 4*j + w
    __shared__ ull swc2[108];            // [cc][o][tap] broadcast pairs

    int bx = blockIdx.x & 7, by = blockIdx.x >> 3;
    int X0 = bx*64, Y0 = by*8;
    int gb = (X0 >> 2) - 1;
    int tid = threadIdx.x;
    int lx = (tid & 15)*4;
    int ly = tid >> 4;
    int jb = lx >> 2;

    ull a01[3], a23[3];
    #pragma unroll
    for (int o = 0; o < 3; o++) {
        float bo = __ldg(&tb[o]);
        a01[o] = pk2(bo, bo);
        a23[o] = pk2(bo, bo);
    }

    for (int chunk = 0; chunk < 16; chunk++) {
        __syncthreads();
        // stage 2 channel-pair planes (4 channels) x 4 phases x 10 rows x 18 j
        for (int idx = tid; idx < 1440; idx += 128) {
            int j   = idx % 18;
            int r   = (idx / 18) % 10;
            int w   = (idx / 180) & 3;
            int c2l = idx / 720;
            int gy = Y0 - 1 + r;
            int gg = gb + j;
            ull v = 0ULL;
            if ((unsigned)gy < 512u && (unsigned)gg < 128u)
                v = g_hidden2[(chunk*2 + c2l)*NPIX + (gy << 9) + (w << 7) + gg];
            float lo, hi; upk2(v, lo, hi);
            sh[w][c2l*2+0][r][j] = lo;
            sh[w][c2l*2+1][r][j] = hi;
        }
        for (int idx = tid; idx < 108; idx += 128) {
            int cc = idx / 27, rem = idx % 27, o = rem / 9, k = rem % 9;
            float wv = __ldg(&tw[(o*64 + chunk*4 + cc)*9 + k]);
            swc2[idx] = pk2(wv, wv);
        }
        __syncthreads();

        #pragma unroll
        for (int cc = 0; cc < 4; cc++) {
            #pragma unroll
            for (int ro = 0; ro < 3; ro++) {
                int r = ly + ro;
                float v0 = sh[3][cc][r][jb];
                float v1 = sh[0][cc][r][jb+1];
                float v2 = sh[1][cc][r][jb+1];
                float v3 = sh[2][cc][r][jb+1];
                float v4 = sh[3][cc][r][jb+1];
                float v5 = sh[0][cc][r][jb+2];
                ull vp0 = pk2(v0,v1), vp1 = pk2(v1,v2), vp2 = pk2(v2,v3);
                ull vp3 = pk2(v3,v4), vp4 = pk2(v4,v5);
                #pragma unroll
                for (int o = 0; o < 3; o++) {
                    const ull* wp = &swc2[(cc*3 + o)*9 + ro*3];
                    ull q0 = wp[0], q1 = wp[1], q2 = wp[2];
                    a01[o] = fma2(vp0, q0, fma2(vp1, q1, fma2(vp2, q2, a01[o])));
                    a23[o] = fma2(vp2, q0, fma2(vp3, q1, fma2(vp4, q2, a23[o])));
                }
            }
        }
    }

    float r0a,r0b,r0c,r0d, r1a,r1b,r1c,r1d, r2a,r2b,r2c,r2d;
    upk2(a01[0], r0a, r0b); upk2(a23[0], r0c, r0d);
    upk2(a01[1], r1a, r1b); upk2(a23[1], r1c, r1d);
    upk2(a01[2], r2a, r2b); upk2(a23[2], r2c, r2d);
    int base = (Y0 + ly)*512 + X0 + lx;
    g_pred4[base+0] = make_float4(r0a, r1a, r2a, 0.0f);
    g_pred4[base+1] = make_float4(r0b, r1b, r2b, 0.0f);
    g_pred4[base+2] = make_float4(r0c, r1c, r2c, 0.0f);
    g_pred4[base+3] = make_float4(r0d, r1d, r2d, 0.0f);
}

// ============ Kernel 5: query gather (nearest, round-half-even) ============
__global__ void gather_q(const float* __restrict__ coord,
                         const float* __restrict__ cell,
                         float* __restrict__ out) {
    int q = blockIdx.x*blockDim.x + threadIdx.x;
    if (q >= NQ) return;
    float cy = __ldg(&coord[q*2+0]);
    float cx = __ldg(&coord[q*2+1]);
    float ly = __ldg(&cell[q*2+0]);
    float lx = __ldg(&cell[q*2+1]);
    float gyq = fminf(fmaxf(cy - ly*0.5f + 1e-6f, -1.0f + 1e-6f), 1.0f - 1e-6f);
    float gxq = fminf(fmaxf(cx - lx*0.5f + 1e-6f, -1.0f + 1e-6f), 1.0f - 1e-6f);
    int xi = (int)rintf((gxq + 1.0f)*0.5f*511.0f);
    int yi = (int)rintf((gyq + 1.0f)*0.5f*511.0f);
    xi = min(max(xi,0),511);
    yi = min(max(yi,0),511);
    float4 v = __ldg(&g_pred4[(yi << 9) + xi]);
    out[q*3+0] = v.x;
    out[q*3+1] = v.y;
    out[q*3+2] = v.z;
}

extern "C" void kernel_launch(void* const* d_in, const int* in_sizes, int n_in,
                              void* d_out, int out_size) {
    const float* inp    = (const float*)d_in[0];
    const float* coord  = (const float*)d_in[1];
    const float* cell   = (const float*)d_in[2];
    const float* enc_w  = (const float*)d_in[3];
    const float* enc_b  = (const float*)d_in[4];
    const float* body_w1= (const float*)d_in[5];
    const float* body_b1= (const float*)d_in[6];
    const float* body_w2= (const float*)d_in[7];
    const float* body_b2= (const float*)d_in[8];
    const float* rout_w = (const float*)d_in[9];
    const float* rout_b = (const float*)d_in[10];
    const float* off_w  = (const float*)d_in[11];
    const float* off_b  = (const float*)d_in[12];
    const float* tail_w = (const float*)d_in[13];
    const float* tail_b = (const float*)d_in[14];
    const float* wcmp   = (const float*)d_in[15];
    const float* wexp   = (const float*)d_in[16];
    float* out = (float*)d_out;

    k_enc_phase<<<513, 256>>>(inp, enc_w, enc_b,
                              body_w1, body_b1, body_w2, body_b2,
                              rout_w, rout_b, off_w, off_b);
    build_ab<<<32, 512>>>(wcmp, wexp);
    main_fused<<<2048, 128>>>();
    tail_conv<<<512, 128>>>(tail_w, tail_b);
    gather_q<<<1024, 256>>>(coord, cell, out);
}

// round 6
// speedup vs baseline: 1.7704x; 1.2978x over previous
#include <cuda_runtime.h>
#include <cuda_bf16.h>

#define HLR 128
#define WLR 128
#define HH 512
#define WH 512
#define CC 64
#define NPIX (HH*WH)      // 262144
#define NQ 262144

typedef unsigned long long ull;

// ---- packed f32x2 helpers (sm_103a: fma.rn.f32x2 -> FFMA2) ----
__device__ __forceinline__ ull pk2(float lo, float hi) {
    ull r; asm("mov.b64 %0, {%1, %2};" : "=l"(r) : "f"(lo), "f"(hi)); return r;
}
__device__ __forceinline__ void upk2(ull v, float& lo, float& hi) {
    asm("mov.b64 {%0, %1}, %2;" : "=f"(lo), "=f"(hi) : "l"(v));
}
__device__ __forceinline__ ull fma2(ull a, ull b, ull c) {
    ull d; asm("fma.rn.f32x2 %0, %1, %2, %3;" : "=l"(d) : "l"(a), "l"(b), "l"(c)); return d;
}
__device__ __forceinline__ ull mul2(ull a, ull b) {
    ull d; asm("mul.rn.f32x2 %0, %1, %2;" : "=l"(d) : "l"(a), "l"(b)); return d;
}

// ---- scratch (device globals: allocation-free) ----
// g_feat2: channel-pair planes [c2][pix], each ull = (ch 2*c2, ch 2*c2+1)
__device__ __align__(16) ull g_feat2[32*HLR*WLR];            // 4 MB
// g_hidden2: channel-pair planes, PHASE-PERMUTED pixels: [c2][y*512 + w*128 + g]
// where x = 4*g + w
__device__ __align__(16) ull g_hidden2[32*NPIX];             // 64 MB
// g_pred4: PHASE-PERMUTED [y*512 + w*128 + g] {o0,o1,o2,-}
__device__ __align__(16) float4 g_pred4[NPIX];               // 4 MB
__device__ float g_off[16*2];
__device__ float g_r[16*4];
__device__ __align__(16) float g_A[16*512];      // [ph][c*8+k]
__device__ __align__(16) float g_B[16*512];      // [ph][k*64+c]

// ============ Kernel 1: encoder conv3x3 (blocks 0..511) + phase MLP (block 512) ============
__global__ void __launch_bounds__(256)
k_enc_phase(const float* __restrict__ inp,
            const float* __restrict__ ew, const float* __restrict__ eb,
            const float* __restrict__ w1, const float* __restrict__ b1,
            const float* __restrict__ w2, const float* __restrict__ b2,
            const float* __restrict__ rw, const float* __restrict__ rb,
            const float* __restrict__ ow, const float* __restrict__ ob) {
    __shared__ float sw[27*64];    // enc weights [j][c]
    __shared__ float sb[64];
    __shared__ float sw2[64*65];   // mlp w2 transposed-padded
    __shared__ float se1[1024];
    __shared__ float se2[1024];
    int t = threadIdx.x;

    if (blockIdx.x < 512) {
        for (int idx = t; idx < 27*64; idx += 256) {
            int j = idx >> 6, c = idx & 63;
            sw[idx] = __ldg(&ew[c*27 + j]);
        }
        if (t < 64) sb[t] = __ldg(&eb[t]);
        __syncthreads();

        int px = blockIdx.x*32 + (t & 31);
        int grp = t >> 5;
        int x = px & 127, y = px >> 7;

        float in[27];
        #pragma unroll
        for (int ci = 0; ci < 3; ci++)
            #pragma unroll
            for (int ky = 0; ky < 3; ky++) {
                int yy = y + ky - 1;
                bool ry = ((unsigned)yy < 128u);
                #pragma unroll
                for (int kx = 0; kx < 3; kx++) {
                    int xx = x + kx - 1;
                    in[ci*9 + ky*3 + kx] = (ry && ((unsigned)xx < 128u))
                        ? __ldg(&inp[(ci*128 + yy)*128 + xx]) : 0.0f;
                }
            }
        #pragma unroll
        for (int u = 0; u < 2; u++) {
            int c4 = grp*2 + u;
            float4 acc = make_float4(sb[c4*4+0], sb[c4*4+1], sb[c4*4+2], sb[c4*4+3]);
            #pragma unroll
            for (int j = 0; j < 27; j++) {
                float fin = in[j];
                const float4 wv = *(const float4*)&sw[j*64 + c4*4];
                acc.x = fmaf(fin, wv.x, acc.x);
                acc.y = fmaf(fin, wv.y, acc.y);
                acc.z = fmaf(fin, wv.z, acc.z);
                acc.w = fmaf(fin, wv.w, acc.w);
            }
            g_feat2[(c4*2+0)*16384 + px] = pk2(acc.x, acc.y);
            g_feat2[(c4*2+1)*16384 + px] = pk2(acc.z, acc.w);
        }
    } else {
        for (int idx = t; idx < 4096; idx += 256) {
            int c = idx >> 6, j = idx & 63;
            sw2[c*65 + j] = __ldg(&w2[idx]);
        }
        #pragma unroll
        for (int it = 0; it < 4; it++) {
            int item = t + it*256;
            int ph = item >> 6, c = item & 63;
            int py = ph >> 2, px = ph & 3;
            float ch = (py + 0.5f)/4.0f; ch = ch - floorf(ch + 0.001f) - 0.5f;
            float cw = (px + 0.5f)/4.0f; cw = cw - floorf(cw + 0.001f) - 0.5f;
            const float cs = 0.25f;
            float s = __ldg(&b1[c]);
            s = fmaf(__ldg(&w1[c*4+0]), cs, s);
            s = fmaf(__ldg(&w1[c*4+1]), cs, s);
            s = fmaf(__ldg(&w1[c*4+2]), ch, s);
            s = fmaf(__ldg(&w1[c*4+3]), cw, s);
            se1[item] = fmaxf(s, 0.0f);
        }
        __syncthreads();
        #pragma unroll
        for (int it = 0; it < 4; it++) {
            int item = t + it*256;
            int ph = item >> 6, c = item & 63;
            float s = __ldg(&b2[c]);
            #pragma unroll 8
            for (int j = 0; j < 64; j++)
                s = fmaf(sw2[c*65 + j], se1[ph*64 + j], s);
            se2[item] = fmaxf(s, 0.0f);
        }
        __syncthreads();
        if (t < 96) {
            int ph = t / 6, which = t % 6;
            if (which < 2) {
                float s = __ldg(&ob[which]);
                for (int j = 0; j < 64; j++)
                    s = fmaf(__ldg(&ow[which*64 + j]), se2[ph*64 + j], s);
                g_off[ph*2 + which] = s;
            } else {
                int e = which - 2;
                float s = __ldg(&rb[e]);
                for (int j = 0; j < 64; j++)
                    s = fmaf(__ldg(&rw[e*64 + j]), se2[ph*64 + j], s);
                g_r[ph*4 + e] = 1.0f/(1.0f + expf(-s));
            }
        }
    }
}

// ============ Kernel 2: build A(r), B(r) per phase ============
__global__ void build_ab(const float* __restrict__ wc, const float* __restrict__ we) {
    int t = blockIdx.x*blockDim.x + threadIdx.x;
    if (t < 8192) {
        int ph = t >> 9, rem = t & 511;
        int c = rem >> 3, k = rem & 7;
        float s = 0.0f;
        #pragma unroll
        for (int e = 0; e < 4; e++)
            s = fmaf(g_r[ph*4+e], __ldg(&we[(e*64 + c)*8 + k]), s);
        g_A[ph*512 + c*8 + k] = s;
    } else {
        int u = t - 8192;
        int ph = u >> 9, rem = u & 511;
        int k = rem >> 6, c = rem & 63;
        float s = 0.0f;
        #pragma unroll
        for (int e = 0; e < 4; e++)
            s = fmaf(g_r[ph*4+e], __ldg(&wc[(e*8 + k)*64 + c]), s);
        g_B[ph*512 + k*64 + c] = s;
    }
}

// ============ Kernel 3: fused grid-sample + expert mixing (2-pass, low-reg) ============
__global__ void __launch_bounds__(128)
main_fused() {
    __shared__ ull sBt[4*264];   // [phl][c2*8+k] = (B[k][2c2], B[k][2c2+1])
    __shared__ ull sAt[4*264];   // [phl][c2*8+k] = (A[2c2][k], A[2c2+1][k])

    int tid = threadIdx.x;
    int p0 = blockIdx.x << 7;
    int y  = p0 >> 9;
    int X0 = p0 & 511;
    int py4 = y & 3;

    const ull* GB = (const ull*)g_B;
    for (int i = tid; i < 1024; i += 128) {
        int phl = i >> 8, ii = i & 255;
        int c2 = ii >> 3, k = ii & 7;
        int ph = py4*4 + phl;
        sBt[phl*264 + ii] = GB[ph*256 + k*32 + c2];
        sAt[phl*264 + ii] = pk2(g_A[ph*512 + (2*c2)*8 + k],
                                g_A[ph*512 + (2*c2+1)*8 + k]);
    }
    __syncthreads();

    int w    = tid >> 5;
    int lane = tid & 31;
    int x = X0 + 4*lane + w;
    int ph = py4*4 + w;

    float off0 = g_off[ph*2+0];
    float off1 = g_off[ph*2+1];

    float xs = ((float)x + 0.5f)*0.25f - 0.5f + off0;
    float ys = ((float)y + 0.5f)*0.25f - 0.5f + off1;
    float x0f = floorf(xs), y0f = floorf(ys);
    float wx1 = xs - x0f, wx0 = 1.0f - wx1;
    float wy1 = ys - y0f, wy0 = 1.0f - wy1;
    int x0 = (int)x0f, y0 = (int)y0f;
    int x1 = x0 + 1, y1 = y0 + 1;
    float mx0 = ((unsigned)x0 < 128u) ? 1.0f : 0.0f;
    float mx1 = ((unsigned)x1 < 128u) ? 1.0f : 0.0f;
    float my0 = ((unsigned)y0 < 128u) ? 1.0f : 0.0f;
    float my1 = ((unsigned)y1 < 128u) ? 1.0f : 0.0f;
    float w00 = wy0*wx0*my0*mx0;
    float w01 = wy0*wx1*my0*mx1;
    float w10 = wy1*wx0*my1*mx0;
    float w11 = wy1*wx1*my1*mx1;
    int xc0 = min(max(x0,0),127), xc1 = min(max(x1,0),127);
    int yc0 = min(max(y0,0),127), yc1 = min(max(y1,0),127);
    int i00 = yc0*128 + xc0, i01 = yc0*128 + xc1;
    int i10 = yc1*128 + xc0, i11 = yc1*128 + xc1;

    ull W00 = pk2(w00,w00), W01 = pk2(w01,w01);
    ull W10 = pk2(w10,w10), W11 = pk2(w11,w11);

    // ---- pass A: accumulate mid = B * fea0 ----
    ull acc[8] = {0,0,0,0,0,0,0,0};
    const ull* Bp = sBt + w*264;
    #pragma unroll
    for (int c2 = 0; c2 < 32; c2++) {
        const ull* fp = g_feat2 + c2*16384;
        ull f = fma2(__ldg(fp+i11), W11,
                fma2(__ldg(fp+i10), W10,
                fma2(__ldg(fp+i01), W01,
                mul2(__ldg(fp+i00), W00))));
        #pragma unroll
        for (int k = 0; k < 8; k++)
            acc[k] = fma2(Bp[c2*8 + k], f, acc[k]);
    }
    ull mdup[8];
    #pragma unroll
    for (int k = 0; k < 8; k++) {
        float lo, hi; upk2(acc[k], lo, hi);
        float s = lo + hi;
        mdup[k] = pk2(s, s);
    }

    // ---- pass B: hidden = fea0 + A*mid, store permuted ----
    int g = (X0 >> 2) + lane;
    ull* H = g_hidden2 + ((y << 9) + (w << 7) + g);
    const ull* Ap = sAt + w*264;
    #pragma unroll
    for (int c2 = 31; c2 >= 0; c2--) {
        const ull* fp = g_feat2 + c2*16384;
        ull h = fma2(__ldg(fp+i11), W11,
                fma2(__ldg(fp+i10), W10,
                fma2(__ldg(fp+i01), W01,
                mul2(__ldg(fp+i00), W00))));
        #pragma unroll
        for (int k = 0; k < 8; k++)
            h = fma2(Ap[c2*8 + k], mdup[k], h);
        H[c2*NPIX] = h;
    }
}

// ============ Kernel 4: tail conv3x3 (64 -> 3), streaming, channel-pair packed ============
// Thread = one x-column (x = 4g + w), 4 output rows. Warp w fixed -> tap planes
// warp-uniform; lanes map to consecutive g -> every LDG.64 fully coalesced.
// Accumulate in (channel-pair) f32x2 space; lo+hi once at the end.
__global__ void __launch_bounds__(128)
tail_conv(const float* __restrict__ tw, const float* __restrict__ tb) {
    __shared__ ull sw2[864];   // [c2][o][ky*3+kx] broadcast pairs

    for (int idx = threadIdx.x; idx < 864; idx += 128) {
        int c2 = idx / 27, rem = idx % 27;
        int o = rem / 9, t9 = rem % 9;
        sw2[idx] = pk2(__ldg(&tw[(o*64 + 2*c2)*9 + t9]),
                       __ldg(&tw[(o*64 + 2*c2+1)*9 + t9]));
    }
    __syncthreads();

    int w    = threadIdx.x >> 5;
    int lane = threadIdx.x & 31;
    int qy = blockIdx.x >> 2;
    int g  = ((blockIdx.x & 3) << 5) + lane;
    int Y0 = qy << 2;

    // column offsets (ull units) within a row; row stride 512
    int oC = (w << 7) + g;
    int oL, oR;
    bool vl = true, vr = true;
    if (w > 0) { oL = ((w-1) << 7) + g; }
    else       { oL = (3 << 7) + g - 1; vl = (g > 0); }
    if (w < 3) { oR = ((w+1) << 7) + g; }
    else       { oR = g + 1; vr = (g < 127); }

    ull acc[4][3];
    #pragma unroll
    for (int r = 0; r < 4; r++)
        #pragma unroll
        for (int o = 0; o < 3; o++) acc[r][o] = 0ULL;

    #pragma unroll 2
    for (int c2 = 0; c2 < 32; c2++) {
        const ull* P = g_hidden2 + c2*NPIX;
        ull vLr[6], vCr[6], vRr[6];
        #pragma unroll
        for (int r = 0; r < 6; r++) {
            int yy = Y0 - 1 + r;
            bool vy = ((unsigned)yy < 512u);
            const ull* R = P + ((long)yy << 9);
            vLr[r] = (vy && vl) ? __ldg(R + oL) : 0ULL;
            vCr[r] =  vy        ? __ldg(R + oC) : 0ULL;
            vRr[r] = (vy && vr) ? __ldg(R + oR) : 0ULL;
        }
        const ull* wp = &sw2[c2*27];
        #pragma unroll
        for (int ky = 0; ky < 3; ky++) {
            #pragma unroll
            for (int o = 0; o < 3; o++) {
                ull w0 = wp[o*9 + ky*3 + 0];
                ull w1 = wp[o*9 + ky*3 + 1];
                ull w2v = wp[o*9 + ky*3 + 2];
                #pragma unroll
                for (int orow = 0; orow < 4; orow++) {
                    int r = orow + ky;
                    acc[orow][o] = fma2(vLr[r], w0,
                                   fma2(vCr[r], w1,
                                   fma2(vRr[r], w2v, acc[orow][o])));
                }
            }
        }
    }

    float b0 = __ldg(&tb[0]), b1 = __ldg(&tb[1]), b2 = __ldg(&tb[2]);
    #pragma unroll
    for (int orow = 0; orow < 4; orow++) {
        float l0,h0,l1,h1,l2,h2;
        upk2(acc[orow][0], l0, h0);
        upk2(acc[orow][1], l1, h1);
        upk2(acc[orow][2], l2, h2);
        g_pred4[((Y0 + orow) << 9) + oC] =
            make_float4(b0 + l0 + h0, b1 + l1 + h1, b2 + l2 + h2, 0.0f);
    }
}

// ============ Kernel 5: query gather (nearest, round-half-even) ============
__global__ void gather_q(const float* __restrict__ coord,
                         const float* __restrict__ cell,
                         float* __restrict__ out) {
    int q = blockIdx.x*blockDim.x + threadIdx.x;
    if (q >= NQ) return;
    float cy = __ldg(&coord[q*2+0]);
    float cx = __ldg(&coord[q*2+1]);
    float ly = __ldg(&cell[q*2+0]);
    float lx = __ldg(&cell[q*2+1]);
    float gyq = fminf(fmaxf(cy - ly*0.5f + 1e-6f, -1.0f + 1e-6f), 1.0f - 1e-6f);
    float gxq = fminf(fmaxf(cx - lx*0.5f + 1e-6f, -1.0f + 1e-6f), 1.0f - 1e-6f);
    int xi = (int)rintf((gxq + 1.0f)*0.5f*511.0f);
    int yi = (int)rintf((gyq + 1.0f)*0.5f*511.0f);
    xi = min(max(xi,0),511);
    yi = min(max(yi,0),511);
    // phase-permuted pred index
    int idx = (yi << 9) + ((xi & 3) << 7) + (xi >> 2);
    float4 v = __ldg(&g_pred4[idx]);
    out[q*3+0] = v.x;
    out[q*3+1] = v.y;
    out[q*3+2] = v.z;
}

extern "C" void kernel_launch(void* const* d_in, const int* in_sizes, int n_in,
                              void* d_out, int out_size) {
    const float* inp    = (const float*)d_in[0];
    const float* coord  = (const float*)d_in[1];
    const float* cell   = (const float*)d_in[2];
    const float* enc_w  = (const float*)d_in[3];
    const float* enc_b  = (const float*)d_in[4];
    const float* body_w1= (const float*)d_in[5];
    const float* body_b1= (const float*)d_in[6];
    const float* body_w2= (const float*)d_in[7];
    const float* body_b2= (const float*)d_in[8];
    const float* rout_w = (const float*)d_in[9];
    const float* rout_b = (const float*)d_in[10];
    const float* off_w  = (const float*)d_in[11];
    const float* off_b  = (const float*)d_in[12];
    const float* tail_w = (const float*)d_in[13];
    const float* tail_b = (const float*)d_in[14];
    const float* wcmp   = (const float*)d_in[15];
    const float* wexp   = (const float*)d_in[16];
    float* out = (float*)d_out;

    k_enc_phase<<<513, 256>>>(inp, enc_w, enc_b,
                              body_w1, body_b1, body_w2, body_b2,
                              rout_w, rout_b, off_w, off_b);
    build_ab<<<32, 512>>>(wcmp, wexp);
    main_fused<<<2048, 128>>>();
    tail_conv<<<512, 128>>>(tail_w, tail_b);
    gather_q<<<1024, 256>>>(coord, cell, out);
}